// round 1
// baseline (speedup 1.0000x reference)
#include <cuda_runtime.h>
#include <cuda_bf16.h>
#include <cstdint>

// Problem constants (fixed by setup_inputs)
#define BATCH   16
#define CIN     64
#define HH      224
#define WW      224
#define COUT    64
#define KS      3
#define PH      64     // patch height
#define PW      64     // patch width

#define TILE_I  32     // output rows per block
#define TILE_J  64     // output cols per block
#define GROUP   4      // c_out per block
#define SM_ROWS (TILE_I + 2)
#define SM_COLS (TILE_J + 2)

// Each block: 256 threads. tx = output col (0..63), ty = row group (0..3).
// Thread computes 8 consecutive output rows x 4 output channels = 32 accumulators,
// using a 3-row register sliding window over the smem input tile:
// 288 FFMA per 66 LDS per input channel -> FFMA-pipe bound.
__global__ __launch_bounds__(256, 2)
void conv_patch_kernel(const float* __restrict__ in,
                       const float* __restrict__ wgt,
                       const float* __restrict__ bias,
                       float* __restrict__ out,
                       const int* __restrict__ p_pad,
                       const int* __restrict__ p_prs,
                       const int* __restrict__ p_pcs)
{
    const int padding = *p_pad;
    const int prs = *p_prs;
    const int pcs = *p_pcs;

    const int tid = threadIdx.x;
    const int tx  = tid & 63;        // output col within tile
    const int ty  = tid >> 6;        // 0..3
    const int tile_i = blockIdx.x * TILE_I;   // 0 or 32
    const int cog    = blockIdx.y;            // 0..15
    const int b      = blockIdx.z;            // 0..15
    const int co0    = cog * GROUP;

    __shared__ float s_in[SM_ROWS][SM_COLS];
    __shared__ float s_w[GROUP][CIN][9];

    // Stage weights for our 4 output channels (2304 floats)
    for (int idx = tid; idx < GROUP * CIN * 9; idx += 256) {
        int g   = idx / (CIN * 9);
        int rem = idx % (CIN * 9);
        s_w[g][rem / 9][rem % 9] = wgt[(size_t)(co0 + g) * CIN * 9 + rem];
    }

    float acc[GROUP][8];
#pragma unroll
    for (int g = 0; g < GROUP; g++) {
        float bz = bias[co0 + g];
#pragma unroll
        for (int dy = 0; dy < 8; dy++) acc[g][dy] = bz;
    }

    // Global input coords of smem tile origin
    const int row0 = prs + tile_i - padding;
    const int col0 = pcs - padding;

    const float* inb = in + (size_t)b * CIN * HH * WW;
    const int ib = ty * 8;   // first smem row this thread consumes

    for (int ci = 0; ci < CIN; ci++) {
        __syncthreads();   // also orders first-iter weight staging
        const float* inc = inb + (size_t)ci * HH * WW;
        // Stage 34x66 input tile with zero padding at borders
        for (int idx = tid; idx < SM_ROWS * SM_COLS; idx += 256) {
            int r = idx / SM_COLS, c = idx % SM_COLS;
            int gr = row0 + r, gc = col0 + c;
            float v = 0.0f;
            if (gr >= 0 && gr < HH && gc >= 0 && gc < WW)
                v = __ldg(&inc[(size_t)gr * WW + gc]);
            s_in[r][c] = v;
        }
        __syncthreads();

        // Weights for this ci -> registers (broadcast LDS, conflict-free)
        float wr[GROUP][9];
#pragma unroll
        for (int g = 0; g < GROUP; g++)
#pragma unroll
            for (int k = 0; k < 9; k++)
                wr[g][k] = s_w[g][ci][k];

        // 3-row sliding window
        float a0 = s_in[ib][tx],     a1 = s_in[ib][tx + 1],     a2 = s_in[ib][tx + 2];
        float b0 = s_in[ib + 1][tx], b1 = s_in[ib + 1][tx + 1], b2 = s_in[ib + 1][tx + 2];
#pragma unroll
        for (int dy = 0; dy < 8; dy++) {
            float c0 = s_in[ib + dy + 2][tx];
            float c1 = s_in[ib + dy + 2][tx + 1];
            float c2 = s_in[ib + dy + 2][tx + 2];
#pragma unroll
            for (int g = 0; g < GROUP; g++) {
                float v = acc[g][dy];
                v += a0 * wr[g][0]; v += a1 * wr[g][1]; v += a2 * wr[g][2];
                v += b0 * wr[g][3]; v += b1 * wr[g][4]; v += b2 * wr[g][5];
                v += c0 * wr[g][6]; v += c1 * wr[g][7]; v += c2 * wr[g][8];
                acc[g][dy] = v;
            }
            a0 = b0; a1 = b1; a2 = b2;
            b0 = c0; b1 = c1; b2 = c2;
        }
    }

    // Write the patch (coalesced along tx)
#pragma unroll
    for (int g = 0; g < GROUP; g++) {
        float* outc = out + ((size_t)b * COUT + (co0 + g)) * HH * WW;
#pragma unroll
        for (int dy = 0; dy < 8; dy++) {
            int orow = prs + tile_i + ib + dy;
            int ocol = pcs + tx;
            outc[(size_t)orow * WW + ocol] = acc[g][dy];
        }
    }
}

extern "C" void kernel_launch(void* const* d_in, const int* in_sizes, int n_in,
                              void* d_out, int out_size)
{
    const float* in_tensor  = (const float*)d_in[0];
    const float* weights    = (const float*)d_in[1];
    const float* biases     = (const float*)d_in[2];
    const float* out_base   = (const float*)d_in[3];
    const int*   p_pad      = (const int*)d_in[4];
    // d_in[5] = stride (==1), d_in[6] = version (==3)
    const int*   p_prs      = (const int*)d_in[7];
    const int*   p_pcs      = (const int*)d_in[8];

    float* out = (float*)d_out;

    // 1) out = out_tensor (zeros outside the patch). D2D async copy, capturable.
    cudaMemcpyAsync(out, out_base, (size_t)out_size * sizeof(float),
                    cudaMemcpyDeviceToDevice);

    // 2) Overwrite the 64x64 patch with conv3x3 + bias.
    dim3 grid(PH / TILE_I, COUT / GROUP, BATCH);
    conv_patch_kernel<<<grid, 256>>>(in_tensor, weights, biases, out,
                                     p_pad, p_prs, p_pcs);
}

// round 2
// speedup vs baseline: 1.1019x; 1.1019x over previous
#include <cuda_runtime.h>
#include <cstdint>

// Fixed problem shape (setup_inputs)
#define BATCH   16
#define CIN     64
#define HH      224
#define WW      224
#define COUT    64
#define PH      64
#define PW      64

#define TILE_I  32
#define GROUP   4
#define SM_ROWS 34
#define SM_COLS 66
#define STAGE_N (SM_ROWS*SM_COLS)   // 2244
#define NTHREADS 256
#define CONV_BLOCKS 512             // 2 row-tiles * 16 cout-groups * 16 batches

// fused-copy geometry: 16*64*224*224/4 = 12,845,056 float4
// 512 blocks * 256 threads = 131072 threads; 12845056 / 131072 = 98 exactly
#define TOTAL_F4   12845056u
#define GSTRIDE    131072u
#define COPY_PER_T 98

// ---------------- PTX helpers ----------------
__device__ __forceinline__ void cp_async4(uint32_t s, const float* g) {
    asm volatile("cp.async.ca.shared.global [%0], [%1], 4;\n" :: "r"(s), "l"(g));
}
__device__ __forceinline__ void cp_commit() {
    asm volatile("cp.async.commit_group;\n" ::);
}
template<int N> __device__ __forceinline__ void cp_wait() {
    asm volatile("cp.async.wait_group %0;\n" :: "n"(N));
}
__device__ __forceinline__ uint64_t pack2(float lo, float hi) {
    uint64_t r; asm("mov.b64 %0, {%1, %2};" : "=l"(r) : "f"(lo), "f"(hi)); return r;
}
__device__ __forceinline__ void unpack2(uint64_t v, float& lo, float& hi) {
    asm("mov.b64 {%0, %1}, %2;" : "=f"(lo), "=f"(hi) : "l"(v));
}
// d = a*b + d (packed f32x2)
__device__ __forceinline__ void fma2(uint64_t& d, uint64_t a, uint64_t b) {
    asm("fma.rn.f32x2 %0, %1, %2, %0;" : "+l"(d) : "l"(a), "l"(b));
}

// stage one 34x66 input tile (zero-padded at borders) via cp.async
__device__ __forceinline__ void stage_tile(const float* __restrict__ inc,
                                           int row0, int col0,
                                           uint32_t sbuf, int tid) {
#pragma unroll
    for (int j = 0; j < 9; j++) {
        int idx = tid + j * NTHREADS;
        if (j < 8 || idx < STAGE_N) {
            int r = idx / SM_COLS;
            int c = idx - r * SM_COLS;
            int gr = row0 + r, gc = col0 + c;
            uint32_t sa = sbuf + (uint32_t)idx * 4u;
            if ((unsigned)gr < (unsigned)HH && (unsigned)gc < (unsigned)WW) {
                cp_async4(sa, inc + gr * WW + gc);
            } else {
                unsigned z = 0;
                asm volatile("st.shared.b32 [%0], %1;\n" :: "r"(sa), "r"(z));
            }
        }
    }
    cp_commit();
}

__global__ __launch_bounds__(256, 2)
void inc_conv_fused_kernel(const float* __restrict__ in,
                           const float* __restrict__ wgt,
                           const float* __restrict__ bias,
                           const float* __restrict__ outsrc,
                           float* __restrict__ out,
                           const int* __restrict__ p_pad,
                           const int* __restrict__ p_prs,
                           const int* __restrict__ p_pcs) {
    const int padding = *p_pad;
    const int prs = *p_prs;
    const int pcs = *p_pcs;

    const int tid = threadIdx.x;
    const int tx = tid & 63;
    const int ty = tid >> 6;
    const int bid = blockIdx.x;

    const int tile = bid & 1;
    const int cog  = (bid >> 1) & 15;
    const int b    = bid >> 5;
    const int co0  = cog * GROUP;
    const int tile_i = tile * TILE_I;

    __shared__ float  s_in[2][STAGE_N];
    __shared__ float2 s_wp[GROUP][CIN][9];   // weights duplicated into both halves

    // stage duplicated weights (2304 scalars)
    for (int idx = tid; idx < GROUP * CIN * 9; idx += NTHREADS) {
        int g = idx / (CIN * 9);
        int rem = idx % (CIN * 9);
        float w = wgt[(size_t)(co0 + g) * (CIN * 9) + rem];
        s_wp[g][rem / 9][rem % 9] = make_float2(w, w);
    }

    const int row0 = prs + tile_i - padding;
    const int col0 = pcs - padding;
    const float* inb = in + (size_t)b * CIN * HH * WW;

    uint32_t sb0 = (uint32_t)__cvta_generic_to_shared(&s_in[0][0]);
    uint32_t sb1 = (uint32_t)__cvta_generic_to_shared(&s_in[1][0]);

    // accumulators: 4 cout * 4 row-pairs, packed {row 2p, row 2p+1}
    uint64_t acc[GROUP][4];
#pragma unroll
    for (int g = 0; g < GROUP; g++) {
        float bz = bias[co0 + g];
        uint64_t pb = pack2(bz, bz);
#pragma unroll
        for (int p = 0; p < 4; p++) acc[g][p] = pb;
    }

    // fused-copy cursor
    const unsigned gthr = (unsigned)bid * NTHREADS + (unsigned)tid;
    unsigned kcopy = 0;

    const int ibr = ty * 8;   // first tile-row this thread owns

    // prologue stage
    stage_tile(inb, row0, col0, sb0, tid);

    for (int ci = 0; ci < CIN; ci++) {
        if (ci + 1 < CIN) {
            stage_tile(inb + (size_t)(ci + 1) * HH * WW, row0, col0,
                       ((ci + 1) & 1) ? sb1 : sb0, tid);
            cp_wait<1>();
        } else {
            cp_wait<0>();
        }

        // ---- fused output copy: 2 float4 per iteration, skip patch ----
#pragma unroll
        for (int t = 0; t < 2; t++) {
            if (kcopy < COPY_PER_T) {
                unsigned i4 = gthr + kcopy * GSTRIDE;
                unsigned rem = i4 % 12544u;            // within one 224x224 plane (f4)
                unsigned h = rem / 56u;
                unsigned w4 = rem - h * 56u;
                unsigned wcol = w4 * 4u;
                bool in_rows = (h >= (unsigned)prs) && (h < (unsigned)(prs + PH));
                bool full_in = in_rows && wcol >= (unsigned)pcs &&
                               (wcol + 4u) <= (unsigned)(pcs + PW);
                if (!full_in) {
                    float4 v = __ldg(((const float4*)outsrc) + i4);
                    bool overlap = in_rows && (wcol + 3u >= (unsigned)pcs) &&
                                   (wcol < (unsigned)(pcs + PW));
                    if (!overlap) {
                        ((float4*)out)[i4] = v;
                    } else {
                        const float* vf = (const float*)&v;
#pragma unroll
                        for (int e = 0; e < 4; e++) {
                            unsigned wc = wcol + e;
                            if (wc < (unsigned)pcs || wc >= (unsigned)(pcs + PW))
                                out[(size_t)i4 * 4 + e] = vf[e];
                        }
                    }
                }
                kcopy++;
            }
        }

        __syncthreads();   // staged data (cp.async + STS + weights) visible

        const float* S = s_in[ci & 1];
        const uint64_t* wbase0 = reinterpret_cast<const uint64_t*>(&s_wp[0][ci][0]);

        // ---------- phase A: row pairs p=0,1 (needs q0..q4) ----------
        uint64_t q[5][3];
        float rprev[3], rkeep[3];
#pragma unroll
        for (int c = 0; c < 3; c++) rprev[c] = S[(ibr + 0) * SM_COLS + tx + c];
#pragma unroll
        for (int r = 0; r < 5; r++) {
            float rcur[3];
#pragma unroll
            for (int c = 0; c < 3; c++) rcur[c] = S[(ibr + r + 1) * SM_COLS + tx + c];
#pragma unroll
            for (int c = 0; c < 3; c++) q[r][c] = pack2(rprev[c], rcur[c]);
#pragma unroll
            for (int c = 0; c < 3; c++) rprev[c] = rcur[c];
        }
#pragma unroll
        for (int c = 0; c < 3; c++) rkeep[c] = rprev[c];   // row 5

#pragma unroll
        for (int g = 0; g < GROUP; g++) {
            const uint64_t* wp = reinterpret_cast<const uint64_t*>(&s_wp[g][ci][0]);
            uint64_t w[9];
#pragma unroll
            for (int k = 0; k < 9; k++) w[k] = wp[k];
#pragma unroll
            for (int p = 0; p < 2; p++)
#pragma unroll
                for (int kr = 0; kr < 3; kr++)
#pragma unroll
                    for (int kc = 0; kc < 3; kc++)
                        fma2(acc[g][p], q[2 * p + kr][kc], w[kr * 3 + kc]);
        }

        // ---------- phase B: row pairs p=2,3 (needs q4..q8) ----------
#pragma unroll
        for (int c = 0; c < 3; c++) q[0][c] = q[4][c];     // q4 -> local 0
#pragma unroll
        for (int c = 0; c < 3; c++) rprev[c] = rkeep[c];   // row 5
#pragma unroll
        for (int r = 5; r < 9; r++) {
            float rcur[3];
#pragma unroll
            for (int c = 0; c < 3; c++) rcur[c] = S[(ibr + r + 1) * SM_COLS + tx + c];
#pragma unroll
            for (int c = 0; c < 3; c++) q[r - 4][c] = pack2(rprev[c], rcur[c]);
#pragma unroll
            for (int c = 0; c < 3; c++) rprev[c] = rcur[c];
        }

#pragma unroll
        for (int g = 0; g < GROUP; g++) {
            const uint64_t* wp = reinterpret_cast<const uint64_t*>(&s_wp[g][ci][0]);
            uint64_t w[9];
#pragma unroll
            for (int k = 0; k < 9; k++) w[k] = wp[k];
#pragma unroll
            for (int p = 2; p < 4; p++)
#pragma unroll
                for (int kr = 0; kr < 3; kr++)
#pragma unroll
                    for (int kc = 0; kc < 3; kc++)
                        fma2(acc[g][p], q[2 * p - 4 + kr][kc], w[kr * 3 + kc]);
        }
        (void)wbase0;

        __syncthreads();   // all reads of this buffer done before re-stage
    }

    // ---------- epilogue: write 64x64 patch ----------
#pragma unroll
    for (int g = 0; g < GROUP; g++) {
        float* outc = out + ((size_t)b * COUT + (co0 + g)) * HH * WW;
#pragma unroll
        for (int p = 0; p < 4; p++) {
            float lo, hi;
            unpack2(acc[g][p], lo, hi);
            int orow = prs + tile_i + ibr + 2 * p;
            int ocol = pcs + tx;
            outc[(size_t)orow * WW + ocol] = lo;
            outc[(size_t)(orow + 1) * WW + ocol] = hi;
        }
    }
}

extern "C" void kernel_launch(void* const* d_in, const int* in_sizes, int n_in,
                              void* d_out, int out_size) {
    const float* in_tensor = (const float*)d_in[0];
    const float* weights   = (const float*)d_in[1];
    const float* biases    = (const float*)d_in[2];
    const float* out_base  = (const float*)d_in[3];
    const int*   p_pad     = (const int*)d_in[4];
    const int*   p_prs     = (const int*)d_in[7];
    const int*   p_pcs     = (const int*)d_in[8];

    float* out = (float*)d_out;

    inc_conv_fused_kernel<<<CONV_BLOCKS, NTHREADS>>>(
        in_tensor, weights, biases, out_base, out, p_pad, p_prs, p_pcs);
}